// round 2
// baseline (speedup 1.0000x reference)
#include <cuda_runtime.h>
#include <cuda_bf16.h>
#include <math.h>

#define NN 20000
#define EE 320000
#define LD 128
#define MAXIT 10

// ---------------- device scratch (no runtime allocation allowed) ----------------
__device__ __align__(16) float g_z[NN * LD];        // encoder output
__device__ __align__(16) float g_h[NN * LD];        // hidden state
__device__ __align__(16) float g_ab[NN * 2 * LD];   // [a | b] per node
__device__ __align__(16) float g_agg[NN * LD];      // aggregated messages
__device__ __align__(16) float g_u[NN];
__device__ __align__(16) float g_v[NN];
__device__ __align__(16) float g_alpha[EE];
__device__ __align__(16) float g_reach[NN];
__device__ int g_mx[NN];       // per-iter max alpha (bits) over incident edges
__device__ int g_mxd[NN];      // final max alpha (bits) over incoming edges
__device__ int g_best[NN];     // min winning edge index
__device__ int g_deg[NN];
__device__ int g_off[NN];
__device__ int g_cursor[NN];
__device__ int g_csrc[EE];     // CSR-by-dst: source node ids

// ---------------- init ----------------
__global__ void init_kernel(const float* __restrict__ s) {
    int idx = blockIdx.x * blockDim.x + threadIdx.x;
    if (idx < NN * LD) g_h[idx] = 0.f;
    if (idx < NN) {
        g_deg[idx] = 0;
        g_reach[idx] = s[idx];
        g_mxd[idx] = 0;
        g_best[idx] = EE;
    }
}

// ---------------- CSR build (by dst) ----------------
__global__ void deg_kernel(const int* __restrict__ dst) {
    int e = blockIdx.x * blockDim.x + threadIdx.x;
    if (e < EE) atomicAdd(&g_deg[dst[e]], 1);
}

__global__ void scan_kernel() {  // single block, 1024 threads
    __shared__ int part[1024];
    int t = threadIdx.x;
    const int chunk = (NN + 1023) / 1024;
    int b0 = t * chunk;
    int s = 0;
    for (int i = 0; i < chunk; i++) {
        int idx = b0 + i;
        if (idx < NN) s += g_deg[idx];
    }
    part[t] = s;
    __syncthreads();
    for (int o = 1; o < 1024; o <<= 1) {
        int v = (t >= o) ? part[t - o] : 0;
        __syncthreads();
        part[t] += v;
        __syncthreads();
    }
    int run = (t == 0) ? 0 : part[t - 1];
    for (int i = 0; i < chunk; i++) {
        int idx = b0 + i;
        if (idx < NN) {
            g_off[idx] = run;
            g_cursor[idx] = run;
            run += g_deg[idx];
        }
    }
}

__global__ void fill_kernel(const int* __restrict__ src, const int* __restrict__ dst) {
    int e = blockIdx.x * blockDim.x + threadIdx.x;
    if (e < EE) {
        int p = atomicAdd(&g_cursor[dst[e]], 1);
        g_csrc[p] = src[e];
    }
}

// ---------------- encoder: z = relu(pos*We0 + reach*We1 + be); also reset mx ----------------
__global__ void encode_kernel(const float* __restrict__ pos,
                              const float* __restrict__ We,
                              const float* __restrict__ be) {
    int idx = blockIdx.x * blockDim.x + threadIdx.x;
    if (idx >= NN * LD) return;
    int n = idx >> 7, l = idx & 127;
    float v = fmaf(pos[n], We[l], fmaf(g_reach[n], We[LD + l], be[l]));
    g_z[idx] = fmaxf(v, 0.f);
    if (l == 0) g_mx[n] = 0;
}

// ---------------- GEMM: ab = [z|h] @ [W1|W2], M=NN, N=256, K=256 ----------------
// BM=128 BN=64 BK=16, 256 threads, 8x4 microtile
__global__ __launch_bounds__(256) void gemm_ab_kernel(const float* __restrict__ W1,
                                                      const float* __restrict__ W2) {
    __shared__ float As[16][132];
    __shared__ float Bs[16][64];
    int m0 = blockIdx.x * 128;
    int j0 = blockIdx.y * 64;
    const float* Bptr;
    int jb;
    if (j0 < 128) { Bptr = W1; jb = j0; } else { Bptr = W2; jb = j0 - 128; }
    int t = threadIdx.x, tx = t & 15, ty = t >> 4;
    float c[8][4] = {};
    for (int kt = 0; kt < 256; kt += 16) {
        const float* Aptr = (kt < 128) ? (g_z + kt) : (g_h + (kt - 128));
#pragma unroll
        for (int r = 0; r < 2; r++) {
            int f = t + r * 256;
            int mloc = f >> 2;
            int k4 = (f & 3) * 4;
            int m = m0 + mloc;
            float4 av = make_float4(0.f, 0.f, 0.f, 0.f);
            if (m < NN) av = *(const float4*)(Aptr + (size_t)m * 128 + k4);
            As[k4 + 0][mloc] = av.x;
            As[k4 + 1][mloc] = av.y;
            As[k4 + 2][mloc] = av.z;
            As[k4 + 3][mloc] = av.w;
        }
        {
            int kk = t >> 4, j4 = (t & 15) * 4;
            *(float4*)&Bs[kk][j4] = *(const float4*)(Bptr + (size_t)(kt + kk) * 128 + jb + j4);
        }
        __syncthreads();
#pragma unroll
        for (int k = 0; k < 16; k++) {
            float4 a0 = *(const float4*)&As[k][ty * 8];
            float4 a1 = *(const float4*)&As[k][ty * 8 + 4];
            float4 b = *(const float4*)&Bs[k][tx * 4];
            float ar[8] = {a0.x, a0.y, a0.z, a0.w, a1.x, a1.y, a1.z, a1.w};
            float br[4] = {b.x, b.y, b.z, b.w};
#pragma unroll
            for (int i = 0; i < 8; i++)
#pragma unroll
                for (int jj = 0; jj < 4; jj++) c[i][jj] = fmaf(ar[i], br[jj], c[i][jj]);
        }
        __syncthreads();
    }
#pragma unroll
    for (int i = 0; i < 8; i++) {
        int m = m0 + ty * 8 + i;
        if (m < NN) {
            float4 v = make_float4(c[i][0], c[i][1], c[i][2], c[i][3]);
            *(float4*)(g_ab + (size_t)m * 256 + j0 + tx * 4) = v;
        }
    }
}

// ---------------- aggregate: agg[n] = relu(max_{in-edges} a[src] + b[n] + bmsg) ----------------
__global__ void aggregate_kernel(const float* __restrict__ bmsg) {
    int n = blockIdx.x;
    int l = threadIdx.x;
    int beg = g_off[n];
    int d = g_deg[n];
    float out = 0.f;
    if (d > 0) {
        float s = -3.4e38f;
        for (int p = 0; p < d; p++) {
            int sn = g_csrc[beg + p];
            s = fmaxf(s, g_ab[(size_t)sn * 256 + l]);
        }
        out = fmaxf(s + g_ab[(size_t)n * 256 + 128 + l] + bmsg[l], 0.f);
    }
    g_agg[(size_t)n * 128 + l] = out;
}

// ---------------- GEMM: h = relu(agg @ Wout + bout), M=NN, N=128, K=128 ----------------
__global__ __launch_bounds__(256) void gemm_h_kernel(const float* __restrict__ Wout,
                                                     const float* __restrict__ bout) {
    __shared__ float As[16][132];
    __shared__ float Bs[16][64];
    int m0 = blockIdx.x * 128;
    int j0 = blockIdx.y * 64;
    int t = threadIdx.x, tx = t & 15, ty = t >> 4;
    float c[8][4] = {};
    for (int kt = 0; kt < 128; kt += 16) {
#pragma unroll
        for (int r = 0; r < 2; r++) {
            int f = t + r * 256;
            int mloc = f >> 2;
            int k4 = (f & 3) * 4;
            int m = m0 + mloc;
            float4 av = make_float4(0.f, 0.f, 0.f, 0.f);
            if (m < NN) av = *(const float4*)(g_agg + (size_t)m * 128 + kt + k4);
            As[k4 + 0][mloc] = av.x;
            As[k4 + 1][mloc] = av.y;
            As[k4 + 2][mloc] = av.z;
            As[k4 + 3][mloc] = av.w;
        }
        {
            int kk = t >> 4, j4 = (t & 15) * 4;
            *(float4*)&Bs[kk][j4] = *(const float4*)(Wout + (size_t)(kt + kk) * 128 + j0 + j4);
        }
        __syncthreads();
#pragma unroll
        for (int k = 0; k < 16; k++) {
            float4 a0 = *(const float4*)&As[k][ty * 8];
            float4 a1 = *(const float4*)&As[k][ty * 8 + 4];
            float4 b = *(const float4*)&Bs[k][tx * 4];
            float ar[8] = {a0.x, a0.y, a0.z, a0.w, a1.x, a1.y, a1.z, a1.w};
            float br[4] = {b.x, b.y, b.z, b.w};
#pragma unroll
            for (int i = 0; i < 8; i++)
#pragma unroll
                for (int jj = 0; jj < 4; jj++) c[i][jj] = fmaf(ar[i], br[jj], c[i][jj]);
        }
        __syncthreads();
    }
#pragma unroll
    for (int i = 0; i < 8; i++) {
        int m = m0 + ty * 8 + i;
        if (m < NN) {
            int j = j0 + tx * 4;
            float4 v;
            v.x = fmaxf(c[i][0] + bout[j + 0], 0.f);
            v.y = fmaxf(c[i][1] + bout[j + 1], 0.f);
            v.z = fmaxf(c[i][2] + bout[j + 2], 0.f);
            v.w = fmaxf(c[i][3] + bout[j + 3], 0.f);
            *(float4*)(g_h + (size_t)m * 128 + j) = v;
        }
    }
}

// ---------------- decoder per-node dots: u = h.Wdec[0:128], v = h.Wdec[128:256] ----------------
__global__ void uv_kernel(const float* __restrict__ Wdec) {
    int gt = blockIdx.x * blockDim.x + threadIdx.x;
    int w = gt >> 5, lane = gt & 31;
    if (w >= NN) return;
    float4 hv = ((const float4*)(g_h + (size_t)w * 128))[lane];
    float4 w1 = ((const float4*)Wdec)[lane];
    float4 w2 = ((const float4*)(Wdec + 128))[lane];
    float pu = hv.x * w1.x + hv.y * w1.y + hv.z * w1.z + hv.w * w1.w;
    float pv = hv.x * w2.x + hv.y * w2.y + hv.z * w2.z + hv.w * w2.w;
#pragma unroll
    for (int o = 16; o; o >>= 1) {
        pu += __shfl_down_sync(0xffffffffu, pu, o);
        pv += __shfl_down_sync(0xffffffffu, pv, o);
    }
    if (lane == 0) {
        g_u[w] = pu;
        g_v[w] = pv;
    }
}

// ---------------- edge alpha + incident-max for reach ----------------
__global__ void alpha_kernel(const int* __restrict__ src, const int* __restrict__ dst,
                             const float* __restrict__ bdec, float* __restrict__ preds_out) {
    int e = blockIdx.x * blockDim.x + threadIdx.x;
    if (e >= EE) return;
    int sn = src[e], dn = dst[e];
    float x = g_u[sn] + g_v[dn] + bdec[0];
    float al = 1.f / (1.f + expf(-x));
    preds_out[e] = al;
    g_alpha[e] = al;
    int bits = __float_as_int(al);   // al > 0, int-bit order == float order
    atomicMax(&g_mx[sn], bits);
    atomicMax(&g_mx[dn], bits);
}

__global__ void reach_kernel() {
    int n = blockIdx.x * blockDim.x + threadIdx.x;
    if (n >= NN) return;
    g_reach[n] = (__int_as_float(g_mx[n]) >= 0.4f) ? 1.f : 0.f;
}

// ---------------- parents (after last iteration) ----------------
__global__ void mxd_kernel(const int* __restrict__ dst) {
    int e = blockIdx.x * blockDim.x + threadIdx.x;
    if (e < EE) atomicMax(&g_mxd[dst[e]], __float_as_int(g_alpha[e]));
}

__global__ void winner_kernel(const int* __restrict__ dst) {
    int e = blockIdx.x * blockDim.x + threadIdx.x;
    if (e >= EE) return;
    if (g_alpha[e] == __int_as_float(g_mxd[dst[e]])) atomicMin(&g_best[dst[e]], e);
}

__global__ void output_kernel(const int* __restrict__ src, float* __restrict__ out_reach,
                              float* __restrict__ out_par) {
    int n = blockIdx.x * blockDim.x + threadIdx.x;
    if (n >= NN) return;
    out_reach[n] = g_reach[n];
    int b = g_best[n];
    out_par[n] = (b < EE) ? (float)src[b] : (float)n;
}

// ---------------- launch ----------------
extern "C" void kernel_launch(void* const* d_in, const int* in_sizes, int n_in,
                              void* d_out, int out_size) {
    const float* pos  = (const float*)d_in[0];
    const float* s    = (const float*)d_in[1];
    const int*   ei   = (const int*)d_in[2];
    const float* Wenc = (const float*)d_in[3];
    const float* benc = (const float*)d_in[4];
    const float* W1   = (const float*)d_in[5];
    const float* W2   = (const float*)d_in[6];
    const float* bmsg = (const float*)d_in[7];
    const float* Wout = (const float*)d_in[8];
    const float* bout = (const float*)d_in[9];
    const float* Wdec = (const float*)d_in[10];
    const float* bdec = (const float*)d_in[11];
    const int* src = ei;
    const int* dst = ei + EE;
    float* out = (float*)d_out;

    const int TB = 256;
    init_kernel<<<(NN * LD + TB - 1) / TB, TB>>>(s);
    deg_kernel<<<(EE + TB - 1) / TB, TB>>>(dst);
    scan_kernel<<<1, 1024>>>();
    fill_kernel<<<(EE + TB - 1) / TB, TB>>>(src, dst);

    dim3 gab((NN + 127) / 128, 4);
    dim3 gh((NN + 127) / 128, 2);
    for (int it = 0; it < MAXIT; it++) {
        encode_kernel<<<(NN * LD + TB - 1) / TB, TB>>>(pos, Wenc, benc);
        gemm_ab_kernel<<<gab, 256>>>(W1, W2);
        aggregate_kernel<<<NN, 128>>>(bmsg);
        gemm_h_kernel<<<gh, 256>>>(Wout, bout);
        uv_kernel<<<(NN * 32 + TB - 1) / TB, TB>>>(Wdec);
        alpha_kernel<<<(EE + TB - 1) / TB, TB>>>(src, dst, bdec, out + (size_t)it * EE);
        reach_kernel<<<(NN + TB - 1) / TB, TB>>>();
    }
    mxd_kernel<<<(EE + TB - 1) / TB, TB>>>(dst);
    winner_kernel<<<(EE + TB - 1) / TB, TB>>>(dst);
    output_kernel<<<(NN + TB - 1) / TB, TB>>>(src, out + 10ull * EE, out + 10ull * EE + NN);
}